// round 4
// baseline (speedup 1.0000x reference)
#include <cuda_runtime.h>
#include <cuda_bf16.h>
#include <stdint.h>

#define B_SZ 4
#define S_SZ 4096
#define D_SZ 1024
#define H_SZ 16
#define K_SZ 64
#define W_SZ 8
#define SW_SZ 512
#define M_ROWS (B_SZ * S_SZ)   // 16384

// ---- scratch: __device__ globals (device allocation is forbidden) ----------
__device__ __nv_bfloat16 g_xb[M_ROWS * D_SZ];
__device__ __nv_bfloat16 g_wq[D_SZ * D_SZ];
__device__ __nv_bfloat16 g_wk[D_SZ * D_SZ];
__device__ __nv_bfloat16 g_wv[D_SZ * D_SZ];
__device__ __nv_bfloat16 g_wo[D_SZ * D_SZ];
__device__ __nv_bfloat16 g_q[M_ROWS * D_SZ];
__device__ __nv_bfloat16 g_k[M_ROWS * D_SZ];
__device__ __nv_bfloat16 g_v[M_ROWS * D_SZ];
__device__ __nv_bfloat16 g_ctx[M_ROWS * D_SZ];

// ---- PTX helpers -----------------------------------------------------------
static __device__ __forceinline__ uint32_t smem_u32(const void* p) {
    return (uint32_t)__cvta_generic_to_shared(p);
}
static __device__ __forceinline__ void ldsm_x4(uint32_t& r0, uint32_t& r1, uint32_t& r2, uint32_t& r3, const void* p) {
    asm volatile("ldmatrix.sync.aligned.m8n8.x4.shared.b16 {%0,%1,%2,%3}, [%4];\n"
                 : "=r"(r0), "=r"(r1), "=r"(r2), "=r"(r3) : "r"(smem_u32(p)));
}
static __device__ __forceinline__ void ldsm_x4t(uint32_t& r0, uint32_t& r1, uint32_t& r2, uint32_t& r3, const void* p) {
    asm volatile("ldmatrix.sync.aligned.m8n8.x4.trans.shared.b16 {%0,%1,%2,%3}, [%4];\n"
                 : "=r"(r0), "=r"(r1), "=r"(r2), "=r"(r3) : "r"(smem_u32(p)));
}
static __device__ __forceinline__ void mma16816(float c[4], const uint32_t a[4], const uint32_t b[2]) {
    asm volatile("mma.sync.aligned.m16n8k16.row.col.f32.bf16.bf16.f32 "
                 "{%0,%1,%2,%3}, {%4,%5,%6,%7}, {%8,%9}, {%0,%1,%2,%3};\n"
                 : "+f"(c[0]), "+f"(c[1]), "+f"(c[2]), "+f"(c[3])
                 : "r"(a[0]), "r"(a[1]), "r"(a[2]), "r"(a[3]), "r"(b[0]), "r"(b[1]));
}
static __device__ __forceinline__ void cp16(const void* sdst, const void* gsrc) {
    asm volatile("cp.async.cg.shared.global [%0], [%1], 16;\n" ::"r"(smem_u32(sdst)), "l"(gsrc));
}
static __device__ __forceinline__ void cp_commit() { asm volatile("cp.async.commit_group;\n"); }
static __device__ __forceinline__ void cp_wait0()  { asm volatile("cp.async.wait_group 0;\n"); }

// ---- fp32 -> bf16 convert --------------------------------------------------
__global__ void cvt4_kernel(const float* __restrict__ in, __nv_bfloat16* __restrict__ out, int n4) {
    int i = blockIdx.x * blockDim.x + threadIdx.x;
    if (i < n4) {
        float4 v = reinterpret_cast<const float4*>(in)[i];
        __nv_bfloat162* o2 = reinterpret_cast<__nv_bfloat162*>(out);
        o2[2 * i]     = __floats2bfloat162_rn(v.x, v.y);
        o2[2 * i + 1] = __floats2bfloat162_rn(v.z, v.w);
    }
}

// ---- NN GEMM: C[16384,1024] = A @ B[1024,1024] -----------------------------
// MODE 0: bf16 out = acc + bias[n].  MODE 1: f32 out = acc + bias[n] + resid.
#define BM 128
#define BN 128
#define BK 32
#define KT (D_SZ / BK)

template <int MODE>
__launch_bounds__(256)
__global__ void gemm_nn_kernel(const __nv_bfloat16* __restrict__ A,
                               const __nv_bfloat16* __restrict__ Bm,
                               const float* __restrict__ bias,
                               const float* __restrict__ resid,
                               void* __restrict__ Cout) {
    const int tn = blockIdx.x * BN, tm = blockIdx.y * BM;
    const int tid = threadIdx.x, lane = tid & 31, warp = tid >> 5;
    const int wm = warp >> 1, wn = warp & 1;   // 4x2 warps; warp tile 32x64

    __shared__ __align__(16) __nv_bfloat16 As[2][BM][BK + 8];
    __shared__ __align__(16) __nv_bfloat16 Bs[2][BK][BN + 8];

    float c[2][8][4];
#pragma unroll
    for (int mi = 0; mi < 2; mi++)
#pragma unroll
        for (int ni = 0; ni < 8; ni++)
#pragma unroll
            for (int j = 0; j < 4; j++) c[mi][ni][j] = 0.f;

    auto load_tiles = [&](int st, int k0) {
#pragma unroll
        for (int i = 0; i < 2; i++) {
            int idx = tid + i * 256;
            int ra = idx >> 2, ca = (idx & 3) * 8;
            cp16(&As[st][ra][ca], A + (size_t)(tm + ra) * D_SZ + k0 + ca);
            int rb = idx >> 4, cb = (idx & 15) * 8;
            cp16(&Bs[st][rb][cb], Bm + (size_t)(k0 + rb) * D_SZ + tn + cb);
        }
        cp_commit();
    };

    load_tiles(0, 0);
    for (int kt = 0; kt < KT; ++kt) {
        cp_wait0();
        __syncthreads();
        if (kt + 1 < KT) load_tiles((kt + 1) & 1, (kt + 1) * BK);
        const int st = kt & 1;
#pragma unroll
        for (int kk = 0; kk < BK; kk += 16) {
            uint32_t a[2][4], b[8][2];
#pragma unroll
            for (int mi = 0; mi < 2; mi++)
                ldsm_x4(a[mi][0], a[mi][1], a[mi][2], a[mi][3],
                        &As[st][wm * 32 + mi * 16 + (lane & 15)][kk + (lane >> 4) * 8]);
#pragma unroll
            for (int nj = 0; nj < 4; nj++) {
                uint32_t r0, r1, r2, r3;
                ldsm_x4t(r0, r1, r2, r3,
                         &Bs[st][kk + (lane & 15)][wn * 64 + nj * 16 + (lane >> 4) * 8]);
                b[2 * nj][0] = r0; b[2 * nj][1] = r1;
                b[2 * nj + 1][0] = r2; b[2 * nj + 1][1] = r3;
            }
#pragma unroll
            for (int mi = 0; mi < 2; mi++)
#pragma unroll
                for (int ni = 0; ni < 8; ni++)
                    mma16816(c[mi][ni], a[mi], b[ni]);
        }
        __syncthreads();
    }

#pragma unroll
    for (int mi = 0; mi < 2; mi++)
#pragma unroll
        for (int ni = 0; ni < 8; ni++) {
            int col = tn + wn * 64 + ni * 8 + 2 * (lane & 3);
            float b0 = bias[col], b1 = bias[col + 1];
#pragma unroll
            for (int h = 0; h < 2; h++) {
                int row = tm + wm * 32 + mi * 16 + (lane >> 2) + h * 8;
                size_t off = (size_t)row * D_SZ + col;
                float v0 = c[mi][ni][h * 2 + 0] + b0;
                float v1 = c[mi][ni][h * 2 + 1] + b1;
                if (MODE == 0) {
                    *reinterpret_cast<__nv_bfloat162*>(
                        reinterpret_cast<__nv_bfloat16*>(Cout) + off) = __floats2bfloat162_rn(v0, v1);
                } else {
                    float2 r = *reinterpret_cast<const float2*>(resid + off);
                    *reinterpret_cast<float2*>(reinterpret_cast<float*>(Cout) + off) =
                        make_float2(v0 + r.x, v1 + r.y);
                }
            }
        }
}

// ---- fused windowed attention ---------------------------------------------
// grid (qt=8, head=16, b*8+w=32); CTA: 64 queries x full 512-key window.
#define QS_STRIDE 72
#define KV_STRIDE 72
#define P_STRIDE 520
#define SMEM_ATTN ((64 * QS_STRIDE + 512 * KV_STRIDE + 512 * KV_STRIDE) * 2)

__launch_bounds__(256)
__global__ void attn_kernel(const __nv_bfloat16* __restrict__ Q,
                            const __nv_bfloat16* __restrict__ Kg,
                            const __nv_bfloat16* __restrict__ Vg,
                            __nv_bfloat16* __restrict__ Ctx) {
    extern __shared__ __align__(16) __nv_bfloat16 smbuf[];
    __nv_bfloat16* Qs  = smbuf;                                    // [64][72]
    __nv_bfloat16* KPs = smbuf + 64 * QS_STRIDE;                   // K[512][72] then P[64][520]
    __nv_bfloat16* Vs  = smbuf + 64 * QS_STRIDE + 512 * KV_STRIDE; // [512][72]
    __shared__ float red[64][8];
    __shared__ float rowstat[64];

    const int tid = threadIdx.x, lane = tid & 31, warp = tid >> 5;
    const int qt = blockIdx.x, head = blockIdx.y, bw = blockIdx.z;
    const int b = bw >> 3, w = bw & 7;
    const size_t rowbase = (size_t)b * S_SZ + (size_t)w * SW_SZ;
    const size_t qrow = rowbase + qt * 64;
    const int colbase = head * K_SZ;

    for (int i = tid; i < 64 * 8; i += 256) {
        int r = i >> 3, c0 = (i & 7) * 8;
        *reinterpret_cast<uint4*>(&Qs[r * QS_STRIDE + c0]) =
            *reinterpret_cast<const uint4*>(&Q[(qrow + r) * D_SZ + colbase + c0]);
    }
    for (int i = tid; i < 512 * 8; i += 256) {
        int r = i >> 3, c0 = (i & 7) * 8;
        *reinterpret_cast<uint4*>(&KPs[r * KV_STRIDE + c0]) =
            *reinterpret_cast<const uint4*>(&Kg[(rowbase + r) * D_SZ + colbase + c0]);
        *reinterpret_cast<uint4*>(&Vs[r * KV_STRIDE + c0]) =
            *reinterpret_cast<const uint4*>(&Vg[(rowbase + r) * D_SZ + colbase + c0]);
    }
    __syncthreads();

    // scores S[64,512] = Q @ K^T ; warp owns cols [warp*64, +64)
    float c[4][8][4];
#pragma unroll
    for (int mi = 0; mi < 4; mi++)
#pragma unroll
        for (int ni = 0; ni < 8; ni++)
#pragma unroll
            for (int j = 0; j < 4; j++) c[mi][ni][j] = 0.f;

#pragma unroll
    for (int kk = 0; kk < K_SZ; kk += 16) {
        uint32_t a[4][4], bfr[8][2];
#pragma unroll
        for (int mi = 0; mi < 4; mi++)
            ldsm_x4(a[mi][0], a[mi][1], a[mi][2], a[mi][3],
                    &Qs[(mi * 16 + (lane & 15)) * QS_STRIDE + kk + (lane >> 4) * 8]);
#pragma unroll
        for (int nb = 0; nb < 4; nb++) {
            int krow = warp * 64 + nb * 16 + ((lane >> 4) << 3) + (lane & 7);
            int kcol = kk + (((lane >> 3) & 1) << 3);
            uint32_t r0, r1, r2, r3;
            ldsm_x4(r0, r1, r2, r3, &KPs[krow * KV_STRIDE + kcol]);
            bfr[2 * nb][0] = r0; bfr[2 * nb][1] = r1;
            bfr[2 * nb + 1][0] = r2; bfr[2 * nb + 1][1] = r3;
        }
#pragma unroll
        for (int mi = 0; mi < 4; mi++)
#pragma unroll
            for (int ni = 0; ni < 8; ni++)
                mma16816(c[mi][ni], a[mi], bfr[ni]);
    }

    // softmax over full 512-wide rows
    const float SCALE = 0.125f;
    float pm[4][2];
#pragma unroll
    for (int mi = 0; mi < 4; mi++)
#pragma unroll
        for (int h = 0; h < 2; h++) {
            float m = -1e30f;
#pragma unroll
            for (int ni = 0; ni < 8; ni++) {
                c[mi][ni][h * 2]     *= SCALE;
                c[mi][ni][h * 2 + 1] *= SCALE;
                m = fmaxf(m, fmaxf(c[mi][ni][h * 2], c[mi][ni][h * 2 + 1]));
            }
            m = fmaxf(m, __shfl_xor_sync(0xffffffffu, m, 1));
            m = fmaxf(m, __shfl_xor_sync(0xffffffffu, m, 2));
            pm[mi][h] = m;
        }
    if ((lane & 3) == 0)
#pragma unroll
        for (int mi = 0; mi < 4; mi++)
#pragma unroll
            for (int h = 0; h < 2; h++)
                red[mi * 16 + h * 8 + (lane >> 2)][warp] = pm[mi][h];
    __syncthreads();
    if (tid < 64) {
        float m = red[tid][0];
#pragma unroll
        for (int ww = 1; ww < 8; ww++) m = fmaxf(m, red[tid][ww]);
        rowstat[tid] = m;
    }
    __syncthreads();

    const float LOG2E = 1.4426950408889634f;
    float ps[4][2];
#pragma unroll
    for (int mi = 0; mi < 4; mi++)
#pragma unroll
        for (int h = 0; h < 2; h++) {
            float rm = rowstat[mi * 16 + h * 8 + (lane >> 2)];
            float s = 0.f;
#pragma unroll
            for (int ni = 0; ni < 8; ni++) {
                float e0 = exp2f((c[mi][ni][h * 2]     - rm) * LOG2E);
                float e1 = exp2f((c[mi][ni][h * 2 + 1] - rm) * LOG2E);
                c[mi][ni][h * 2] = e0; c[mi][ni][h * 2 + 1] = e1;
                s += e0 + e1;
            }
            s += __shfl_xor_sync(0xffffffffu, s, 1);
            s += __shfl_xor_sync(0xffffffffu, s, 2);
            ps[mi][h] = s;
        }
    if ((lane & 3) == 0)
#pragma unroll
        for (int mi = 0; mi < 4; mi++)
#pragma unroll
            for (int h = 0; h < 2; h++)
                red[mi * 16 + h * 8 + (lane >> 2)][warp] = ps[mi][h];
    // store unnormalized P into the (dead) K smem region
#pragma unroll
    for (int mi = 0; mi < 4; mi++)
#pragma unroll
        for (int ni = 0; ni < 8; ni++)
#pragma unroll
            for (int h = 0; h < 2; h++) {
                int row = mi * 16 + h * 8 + (lane >> 2);
                int col = warp * 64 + ni * 8 + 2 * (lane & 3);
                *reinterpret_cast<__nv_bfloat162*>(&KPs[row * P_STRIDE + col]) =
                    __floats2bfloat162_rn(c[mi][ni][h * 2], c[mi][ni][h * 2 + 1]);
            }
    __syncthreads();
    if (tid < 64) {
        float s = 0.f;
#pragma unroll
        for (int ww = 0; ww < 8; ww++) s += red[tid][ww];
        rowstat[tid] = s;
    }
    __syncthreads();

    // ctx[64,64] = P[64,512] @ V[512,64] ; warps 2(m) x 4(n)
    const int wm2 = warp >> 2, wn2 = warp & 3;
    float d[2][2][4];
#pragma unroll
    for (int mi = 0; mi < 2; mi++)
#pragma unroll
        for (int nj = 0; nj < 2; nj++)
#pragma unroll
            for (int j = 0; j < 4; j++) d[mi][nj][j] = 0.f;

#pragma unroll 4
    for (int kk = 0; kk < SW_SZ; kk += 16) {
        uint32_t a2[2][4];
#pragma unroll
        for (int mi = 0; mi < 2; mi++)
            ldsm_x4(a2[mi][0], a2[mi][1], a2[mi][2], a2[mi][3],
                    &KPs[(wm2 * 32 + mi * 16 + (lane & 15)) * P_STRIDE + kk + (lane >> 4) * 8]);
        uint32_t r0, r1, r2, r3;
        ldsm_x4t(r0, r1, r2, r3,
                 &Vs[(kk + (lane & 15)) * KV_STRIDE + wn2 * 16 + (lane >> 4) * 8]);
        uint32_t b0[2] = {r0, r1}, b1[2] = {r2, r3};
#pragma unroll
        for (int mi = 0; mi < 2; mi++) {
            mma16816(d[mi][0], a2[mi], b0);
            mma16816(d[mi][1], a2[mi], b1);
        }
    }

#pragma unroll
    for (int mi = 0; mi < 2; mi++)
#pragma unroll
        for (int h = 0; h < 2; h++) {
            int rl = wm2 * 32 + mi * 16 + h * 8 + (lane >> 2);
            float rinv = 1.0f / rowstat[rl];
            size_t grow = (qrow + rl) * D_SZ;
#pragma unroll
            for (int nj = 0; nj < 2; nj++) {
                int col = colbase + wn2 * 16 + nj * 8 + 2 * (lane & 3);
                *reinterpret_cast<__nv_bfloat162*>(&Ctx[grow + col]) =
                    __floats2bfloat162_rn(d[mi][nj][h * 2] * rinv, d[mi][nj][h * 2 + 1] * rinv);
            }
        }
}

// ---- LayerNorm (in place on d_out), eps = 1e-3 -----------------------------
__launch_bounds__(256)
__global__ void ln_kernel(float* __restrict__ y,
                          const float* __restrict__ gamma,
                          const float* __restrict__ beta) {
    const int row = blockIdx.x, t = threadIdx.x;
    float4 v = reinterpret_cast<const float4*>(y + (size_t)row * D_SZ)[t];
    float s = v.x + v.y + v.z + v.w;
    float q = v.x * v.x + v.y * v.y + v.z * v.z + v.w * v.w;
#pragma unroll
    for (int o = 16; o; o >>= 1) {
        s += __shfl_xor_sync(0xffffffffu, s, o);
        q += __shfl_xor_sync(0xffffffffu, q, o);
    }
    __shared__ float ss[8], sq[8];
    int warp = t >> 5, lane = t & 31;
    if (lane == 0) { ss[warp] = s; sq[warp] = q; }
    __syncthreads();
    float ts = 0.f, tq = 0.f;
#pragma unroll
    for (int ww = 0; ww < 8; ww++) { ts += ss[ww]; tq += sq[ww]; }
    float mu = ts * (1.0f / D_SZ);
    float var = tq * (1.0f / D_SZ) - mu * mu;
    float rstd = rsqrtf(var + 1e-3f);
    float4 g  = reinterpret_cast<const float4*>(gamma)[t];
    float4 be = reinterpret_cast<const float4*>(beta)[t];
    float4 o;
    o.x = (v.x - mu) * rstd * g.x + be.x;
    o.y = (v.y - mu) * rstd * g.y + be.y;
    o.z = (v.z - mu) * rstd * g.z + be.z;
    o.w = (v.w - mu) * rstd * g.w + be.w;
    reinterpret_cast<float4*>(y + (size_t)row * D_SZ)[t] = o;
}

// ---- host launcher ---------------------------------------------------------
extern "C" void kernel_launch(void* const* d_in, const int* in_sizes, int n_in,
                              void* d_out, int out_size) {
    const float* x     = (const float*)d_in[0];
    const float* Wq    = (const float*)d_in[1];
    const float* bq    = (const float*)d_in[2];
    const float* Wk    = (const float*)d_in[3];
    const float* bk    = (const float*)d_in[4];
    const float* Wv    = (const float*)d_in[5];
    const float* bv    = (const float*)d_in[6];
    const float* Wo    = (const float*)d_in[7];
    const float* bo    = (const float*)d_in[8];
    const float* gamma = (const float*)d_in[9];
    const float* beta  = (const float*)d_in[10];
    float* out = (float*)d_out;

    void *xb, *wq, *wk, *wv, *wo, *qb, *kb, *vb, *ctxb;
    cudaGetSymbolAddress(&xb, g_xb);
    cudaGetSymbolAddress(&wq, g_wq);
    cudaGetSymbolAddress(&wk, g_wk);
    cudaGetSymbolAddress(&wv, g_wv);
    cudaGetSymbolAddress(&wo, g_wo);
    cudaGetSymbolAddress(&qb, g_q);
    cudaGetSymbolAddress(&kb, g_k);
    cudaGetSymbolAddress(&vb, g_v);
    cudaGetSymbolAddress(&ctxb, g_ctx);

    cvt4_kernel<<<(M_ROWS * D_SZ / 4) / 256, 256>>>(x, (__nv_bfloat16*)xb, M_ROWS * D_SZ / 4);
    cvt4_kernel<<<(D_SZ * D_SZ / 4) / 256, 256>>>(Wq, (__nv_bfloat16*)wq, D_SZ * D_SZ / 4);
    cvt4_kernel<<<(D_SZ * D_SZ / 4) / 256, 256>>>(Wk, (__nv_bfloat16*)wk, D_SZ * D_SZ / 4);
    cvt4_kernel<<<(D_SZ * D_SZ / 4) / 256, 256>>>(Wv, (__nv_bfloat16*)wv, D_SZ * D_SZ / 4);
    cvt4_kernel<<<(D_SZ * D_SZ / 4) / 256, 256>>>(Wo, (__nv_bfloat16*)wo, D_SZ * D_SZ / 4);

    dim3 gg(D_SZ / BN, M_ROWS / BM);
    gemm_nn_kernel<0><<<gg, 256>>>((const __nv_bfloat16*)xb, (const __nv_bfloat16*)wq, bq, nullptr, qb);
    gemm_nn_kernel<0><<<gg, 256>>>((const __nv_bfloat16*)xb, (const __nv_bfloat16*)wk, bk, nullptr, kb);
    gemm_nn_kernel<0><<<gg, 256>>>((const __nv_bfloat16*)xb, (const __nv_bfloat16*)wv, bv, nullptr, vb);

    cudaFuncSetAttribute(attn_kernel, cudaFuncAttributeMaxDynamicSharedMemorySize, SMEM_ATTN);
    attn_kernel<<<dim3(SW_SZ / 64, H_SZ, B_SZ * W_SZ), 256, SMEM_ATTN>>>(
        (const __nv_bfloat16*)qb, (const __nv_bfloat16*)kb, (const __nv_bfloat16*)vb,
        (__nv_bfloat16*)ctxb);

    gemm_nn_kernel<1><<<gg, 256>>>((const __nv_bfloat16*)ctxb, (const __nv_bfloat16*)wo, bo, x, out);

    ln_kernel<<<M_ROWS, 256>>>(out, gamma, beta);
}

// round 6
// speedup vs baseline: 1.1424x; 1.1424x over previous
#include <cuda_runtime.h>
#include <cuda_bf16.h>
#include <stdint.h>

#define B_SZ 4
#define S_SZ 4096
#define D_SZ 1024
#define H_SZ 16
#define K_SZ 64
#define W_SZ 8
#define SW_SZ 512
#define M_ROWS (B_SZ * S_SZ)   // 16384

// ---- scratch ----------------------------------------------------------------
__device__ __nv_bfloat16 g_xb[M_ROWS * D_SZ];
__device__ __nv_bfloat16 g_wq[D_SZ * D_SZ];
__device__ __nv_bfloat16 g_wk[D_SZ * D_SZ];
__device__ __nv_bfloat16 g_wv[D_SZ * D_SZ];
__device__ __nv_bfloat16 g_wo[D_SZ * D_SZ];
__device__ __nv_bfloat16 g_q[M_ROWS * D_SZ];
__device__ __nv_bfloat16 g_k[M_ROWS * D_SZ];
__device__ __nv_bfloat16 g_v[M_ROWS * D_SZ];
__device__ __nv_bfloat16 g_ctx[M_ROWS * D_SZ];

// ---- PTX helpers (mma.sync path only — tcgen05 is rejected by this ptxas) ---
static __device__ __forceinline__ uint32_t smem_u32(const void* p) {
    return (uint32_t)__cvta_generic_to_shared(p);
}
static __device__ __forceinline__ void ldsm_x4(uint32_t& r0, uint32_t& r1, uint32_t& r2, uint32_t& r3, const void* p) {
    asm volatile("ldmatrix.sync.aligned.m8n8.x4.shared.b16 {%0,%1,%2,%3}, [%4];\n"
                 : "=r"(r0), "=r"(r1), "=r"(r2), "=r"(r3) : "r"(smem_u32(p)));
}
static __device__ __forceinline__ void ldsm_x4t(uint32_t& r0, uint32_t& r1, uint32_t& r2, uint32_t& r3, const void* p) {
    asm volatile("ldmatrix.sync.aligned.m8n8.x4.trans.shared.b16 {%0,%1,%2,%3}, [%4];\n"
                 : "=r"(r0), "=r"(r1), "=r"(r2), "=r"(r3) : "r"(smem_u32(p)));
}
static __device__ __forceinline__ void mma16816(float c[4], const uint32_t a[4], const uint32_t b[2]) {
    asm volatile("mma.sync.aligned.m16n8k16.row.col.f32.bf16.bf16.f32 "
                 "{%0,%1,%2,%3}, {%4,%5,%6,%7}, {%8,%9}, {%0,%1,%2,%3};\n"
                 : "+f"(c[0]), "+f"(c[1]), "+f"(c[2]), "+f"(c[3])
                 : "r"(a[0]), "r"(a[1]), "r"(a[2]), "r"(a[3]), "r"(b[0]), "r"(b[1]));
}
static __device__ __forceinline__ void cp16(const void* sdst, const void* gsrc) {
    asm volatile("cp.async.cg.shared.global [%0], [%1], 16;\n" ::"r"(smem_u32(sdst)), "l"(gsrc));
}
static __device__ __forceinline__ void cp_commit() { asm volatile("cp.async.commit_group;\n"); }
static __device__ __forceinline__ void cp_wait0()  { asm volatile("cp.async.wait_group 0;\n"); }
static __device__ __forceinline__ void cp_wait1()  { asm volatile("cp.async.wait_group 1;\n"); }

// ---- fp32 -> bf16 convert ---------------------------------------------------
__global__ void cvt4_kernel(const float* __restrict__ in, __nv_bfloat16* __restrict__ out, int n4) {
    int i = blockIdx.x * blockDim.x + threadIdx.x;
    if (i < n4) {
        float4 v = reinterpret_cast<const float4*>(in)[i];
        __nv_bfloat162* o2 = reinterpret_cast<__nv_bfloat162*>(out);
        o2[2 * i]     = __floats2bfloat162_rn(v.x, v.y);
        o2[2 * i + 1] = __floats2bfloat162_rn(v.z, v.w);
    }
}

// ---- NN GEMM: C[16384,1024] = A @ B[1024,1024], warp tile 64x64 -------------
// MODE 0: bf16 out = acc + bias[n].  MODE 1: f32 out = acc + bias[n] + resid.
#define BM 128
#define BN 256
#define BK 32
#define KT (D_SZ / BK)          // 32
#define NSTG 3
#define AS_STRIDE (BK + 8)      // 40
#define BS_STRIDE (BN + 8)      // 264
#define SMEM_GEMM ((NSTG * BM * AS_STRIDE + NSTG * BK * BS_STRIDE) * 2 + 16)

template <int MODE>
__launch_bounds__(256)
__global__ void gemm_nn_kernel(const __nv_bfloat16* __restrict__ A,
                               const __nv_bfloat16* __restrict__ Bm,
                               const float* __restrict__ bias,
                               const float* __restrict__ resid,
                               void* __restrict__ Cout) {
    extern __shared__ __align__(16) __nv_bfloat16 gsm[];
    __nv_bfloat16* As = gsm;                              // [NSTG][BM][AS_STRIDE]
    __nv_bfloat16* Bs = gsm + NSTG * BM * AS_STRIDE;      // [NSTG][BK][BS_STRIDE]

    const int tn = blockIdx.x * BN, tm = blockIdx.y * BM;
    const int tid = threadIdx.x, lane = tid & 31, warp = tid >> 5;
    const int wm = warp >> 2, wn = warp & 3;   // 2x4 warps; warp tile 64x64

    float c[4][8][4];
#pragma unroll
    for (int mi = 0; mi < 4; mi++)
#pragma unroll
        for (int ni = 0; ni < 8; ni++)
#pragma unroll
            for (int j = 0; j < 4; j++) c[mi][ni][j] = 0.f;

    auto load_stage = [&](int s, int k0) {
        __nv_bfloat16* as = As + s * BM * AS_STRIDE;
        __nv_bfloat16* bs = Bs + s * BK * BS_STRIDE;
#pragma unroll
        for (int t = 0; t < 2; t++) {           // A: 128 x 32 (8KB)
            int idx = tid + t * 256;
            int r = idx >> 2, ca = (idx & 3) * 8;
            cp16(&as[r * AS_STRIDE + ca], A + (size_t)(tm + r) * D_SZ + k0 + ca);
        }
#pragma unroll
        for (int t = 0; t < 4; t++) {           // B: 32 x 256 (16KB)
            int idx = tid + t * 256;
            int r = idx >> 5, cb = (idx & 31) * 8;
            cp16(&bs[r * BS_STRIDE + cb], Bm + (size_t)(k0 + r) * D_SZ + tn + cb);
        }
        cp_commit();
    };

    load_stage(0, 0);
    load_stage(1, BK);

    for (int kt = 0; kt < KT; ++kt) {
        cp_wait1();               // stage kt ready (one younger group may pend)
        __syncthreads();          // all warps past iter kt-1 -> slot (kt+2)%3 free
        if (kt + 2 < KT) load_stage((kt + 2) % NSTG, (kt + 2) * BK);

        const __nv_bfloat16* as = As + (kt % NSTG) * BM * AS_STRIDE;
        const __nv_bfloat16* bs = Bs + (kt % NSTG) * BK * BS_STRIDE;
#pragma unroll
        for (int kk = 0; kk < BK; kk += 16) {
            uint32_t a[4][4], b[8][2];
#pragma unroll
            for (int mi = 0; mi < 4; mi++)
                ldsm_x4(a[mi][0], a[mi][1], a[mi][2], a[mi][3],
                        &as[(wm * 64 + mi * 16 + (lane & 15)) * AS_STRIDE + kk + (lane >> 4) * 8]);
#pragma unroll
            for (int nj = 0; nj < 4; nj++) {
                uint32_t r0, r1, r2, r3;
                ldsm_x4t(r0, r1, r2, r3,
                         &bs[(kk + (lane & 15)) * BS_STRIDE + wn * 64 + nj * 16 + (lane >> 4) * 8]);
                b[2 * nj][0] = r0; b[2 * nj][1] = r1;
                b[2 * nj + 1][0] = r2; b[2 * nj + 1][1] = r3;
            }
#pragma unroll
            for (int mi = 0; mi < 4; mi++)
#pragma unroll
                for (int ni = 0; ni < 8; ni++)
                    mma16816(c[mi][ni], a[mi], b[ni]);
        }
    }

#pragma unroll
    for (int mi = 0; mi < 4; mi++)
#pragma unroll
        for (int ni = 0; ni < 8; ni++) {
            int col = tn + wn * 64 + ni * 8 + 2 * (lane & 3);
            float b0 = bias[col], b1 = bias[col + 1];
#pragma unroll
            for (int h = 0; h < 2; h++) {
                int row = tm + wm * 64 + mi * 16 + (lane >> 2) + h * 8;
                size_t off = (size_t)row * D_SZ + col;
                float v0 = c[mi][ni][h * 2 + 0] + b0;
                float v1 = c[mi][ni][h * 2 + 1] + b1;
                if (MODE == 0) {
                    *reinterpret_cast<__nv_bfloat162*>(
                        reinterpret_cast<__nv_bfloat16*>(Cout) + off) = __floats2bfloat162_rn(v0, v1);
                } else {
                    float2 r = *reinterpret_cast<const float2*>(resid + off);
                    *reinterpret_cast<float2*>(reinterpret_cast<float*>(Cout) + off) =
                        make_float2(v0 + r.x, v1 + r.y);
                }
            }
        }
}

// ---- fused windowed attention (R4 structure + cp.async loads) ---------------
#define QS_STRIDE 72
#define KV_STRIDE 72
#define P_STRIDE 520
#define SMEM_ATTN ((64 * QS_STRIDE + 512 * KV_STRIDE + 512 * KV_STRIDE) * 2)

__launch_bounds__(256)
__global__ void attn_kernel(const __nv_bfloat16* __restrict__ Q,
                            const __nv_bfloat16* __restrict__ Kg,
                            const __nv_bfloat16* __restrict__ Vg,
                            __nv_bfloat16* __restrict__ Ctx) {
    extern __shared__ __align__(16) __nv_bfloat16 smbuf[];
    __nv_bfloat16* Qs  = smbuf;
    __nv_bfloat16* KPs = smbuf + 64 * QS_STRIDE;
    __nv_bfloat16* Vs  = smbuf + 64 * QS_STRIDE + 512 * KV_STRIDE;
    __shared__ float red[64][8];
    __shared__ float rowstat[64];

    const int tid = threadIdx.x, lane = tid & 31, warp = tid >> 5;
    const int qt = blockIdx.x, head = blockIdx.y, bw = blockIdx.z;
    const int b = bw >> 3, w = bw & 7;
    const size_t rowbase = (size_t)b * S_SZ + (size_t)w * SW_SZ;
    const size_t qrow = rowbase + qt * 64;
    const int colbase = head * K_SZ;

    // async fills: Q 64x64, K/V 512x64 (16B chunks; strides 72*2=144B, 16B-aligned)
    for (int i = tid; i < 64 * 8; i += 256) {
        int r = i >> 3, c0 = (i & 7) * 8;
        cp16(&Qs[r * QS_STRIDE + c0], &Q[(qrow + r) * D_SZ + colbase + c0]);
    }
    for (int i = tid; i < 512 * 8; i += 256) {
        int r = i >> 3, c0 = (i & 7) * 8;
        cp16(&KPs[r * KV_STRIDE + c0], &Kg[(rowbase + r) * D_SZ + colbase + c0]);
        cp16(&Vs[r * KV_STRIDE + c0], &Vg[(rowbase + r) * D_SZ + colbase + c0]);
    }
    cp_commit();
    cp_wait0();
    __syncthreads();

    // scores S[64,512] = Q @ K^T ; warp owns cols [warp*64, +64)
    float c[4][8][4];
#pragma unroll
    for (int mi = 0; mi < 4; mi++)
#pragma unroll
        for (int ni = 0; ni < 8; ni++)
#pragma unroll
            for (int j = 0; j < 4; j++) c[mi][ni][j] = 0.f;

#pragma unroll
    for (int kk = 0; kk < K_SZ; kk += 16) {
        uint32_t a[4][4], bfr[8][2];
#pragma unroll
        for (int mi = 0; mi < 4; mi++)
            ldsm_x4(a[mi][0], a[mi][1], a[mi][2], a[mi][3],
                    &Qs[(mi * 16 + (lane & 15)) * QS_STRIDE + kk + (lane >> 4) * 8]);
#pragma unroll
        for (int nb = 0; nb < 4; nb++) {
            int krow = warp * 64 + nb * 16 + ((lane >> 4) << 3) + (lane & 7);
            int kcol = kk + (((lane >> 3) & 1) << 3);
            uint32_t r0, r1, r2, r3;
            ldsm_x4(r0, r1, r2, r3, &KPs[krow * KV_STRIDE + kcol]);
            bfr[2 * nb][0] = r0; bfr[2 * nb][1] = r1;
            bfr[2 * nb + 1][0] = r2; bfr[2 * nb + 1][1] = r3;
        }
#pragma unroll
        for (int mi = 0; mi < 4; mi++)
#pragma unroll
            for (int ni = 0; ni < 8; ni++)
                mma16816(c[mi][ni], a[mi], bfr[ni]);
    }

    const float SCALE = 0.125f;
    float pm[4][2];
#pragma unroll
    for (int mi = 0; mi < 4; mi++)
#pragma unroll
        for (int h = 0; h < 2; h++) {
            float m = -1e30f;
#pragma unroll
            for (int ni = 0; ni < 8; ni++) {
                c[mi][ni][h * 2]     *= SCALE;
                c[mi][ni][h * 2 + 1] *= SCALE;
                m = fmaxf(m, fmaxf(c[mi][ni][h * 2], c[mi][ni][h * 2 + 1]));
            }
            m = fmaxf(m, __shfl_xor_sync(0xffffffffu, m, 1));
            m = fmaxf(m, __shfl_xor_sync(0xffffffffu, m, 2));
            pm[mi][h] = m;
        }
    if ((lane & 3) == 0)
#pragma unroll
        for (int mi = 0; mi < 4; mi++)
#pragma unroll
            for (int h = 0; h < 2; h++)
                red[mi * 16 + h * 8 + (lane >> 2)][warp] = pm[mi][h];
    __syncthreads();
    if (tid < 64) {
        float m = red[tid][0];
#pragma unroll
        for (int ww = 1; ww < 8; ww++) m = fmaxf(m, red[tid][ww]);
        rowstat[tid] = m;
    }
    __syncthreads();

    const float LOG2E = 1.4426950408889634f;
    float ps[4][2];
#pragma unroll
    for (int mi = 0; mi < 4; mi++)
#pragma unroll
        for (int h = 0; h < 2; h++) {
            float rm = rowstat[mi * 16 + h * 8 + (lane >> 2)];
            float s = 0.f;
#pragma unroll
            for (int ni = 0; ni < 8; ni++) {
                float e0 = exp2f((c[mi][ni][h * 2]     - rm) * LOG2E);
                float e1 = exp2f((c[mi][ni][h * 2 + 1] - rm) * LOG2E);
                c[mi][ni][h * 2] = e0; c[mi][ni][h * 2 + 1] = e1;
                s += e0 + e1;
            }
            s += __shfl_xor_sync(0xffffffffu, s, 1);
            s += __shfl_xor_sync(0xffffffffu, s, 2);
            ps[mi][h] = s;
        }
    if ((lane & 3) == 0)
#pragma unroll
        for (int mi = 0; mi < 4; mi++)
#pragma unroll
            for (int h = 0; h < 2; h++)
                red[mi * 16 + h * 8 + (lane >> 2)][warp] = ps[mi][h];
#pragma unroll
    for (int mi = 0; mi < 4; mi++)
#pragma unroll
        for (int ni = 0; ni < 8; ni++)
#pragma unroll
            for (int h = 0; h < 2; h++) {
                int row = mi * 16 + h * 8 + (lane >> 2);
                int col = warp * 64 + ni * 8 + 2 * (lane & 3);
                *reinterpret_cast<__nv_bfloat162*>(&KPs[row * P_STRIDE + col]) =
                    __floats2bfloat162_rn(c[mi][ni][h * 2], c[mi][ni][h * 2 + 1]);
            }
    __syncthreads();
    if (tid < 64) {
        float s = 0.f;
#pragma unroll
        for (int ww = 0; ww < 8; ww++) s += red[tid][ww];
        rowstat[tid] = s;
    }
    __syncthreads();

    const int wm2 = warp >> 2, wn2 = warp & 3;
    float d[2][2][4];
#pragma unroll
    for (int mi = 0; mi < 2; mi++)
#pragma unroll
        for (int nj = 0; nj < 2; nj++)
#pragma unroll
            for (int j = 0; j < 4; j++) d[mi][nj][j] = 0.f;

#pragma unroll 4
    for (int kk = 0; kk < SW_SZ; kk += 16) {
        uint32_t a2[2][4];
#pragma unroll
        for (int mi = 0; mi < 2; mi++)
            ldsm_x4(a2[mi][0], a2[mi][1], a2[mi][2], a2[mi][3],
                    &KPs[(wm2 * 32 + mi * 16 + (lane & 15)) * P_STRIDE + kk + (lane >> 4) * 8]);
        uint32_t r0, r1, r2, r3;
        ldsm_x4t(r0, r1, r2, r3,
                 &Vs[(kk + (lane & 15)) * KV_STRIDE + wn2 * 16 + (lane >> 4) * 8]);
        uint32_t b0[2] = {r0, r1}, b1[2] = {r2, r3};
#pragma unroll
        for (int mi = 0; mi < 2; mi++) {
            mma16816(d[mi][0], a2[mi], b0);
            mma16816(d[mi][1], a2[mi], b1);
        }
    }

#pragma unroll
    for (int mi = 0; mi < 2; mi++)
#pragma unroll
        for (int h = 0; h < 2; h++) {
            int rl = wm2 * 32 + mi * 16 + h * 8 + (lane >> 2);
            float rinv = 1.0f / rowstat[rl];
            size_t grow = (qrow + rl) * D_SZ;
#pragma unroll
            for (int nj = 0; nj < 2; nj++) {
                int col = colbase + wn2 * 16 + nj * 8 + 2 * (lane & 3);
                *reinterpret_cast<__nv_bfloat162*>(&Ctx[grow + col]) =
                    __floats2bfloat162_rn(d[mi][nj][h * 2] * rinv, d[mi][nj][h * 2 + 1] * rinv);
            }
        }
}

// ---- LayerNorm (in place), eps = 1e-3 ---------------------------------------
__launch_bounds__(256)
__global__ void ln_kernel(float* __restrict__ y,
                          const float* __restrict__ gamma,
                          const float* __restrict__ beta) {
    const int row = blockIdx.x, t = threadIdx.x;
    float4 v = reinterpret_cast<const float4*>(y + (size_t)row * D_SZ)[t];
    float s = v.x + v.y + v.z + v.w;
    float q = v.x * v.x + v.y * v.y + v.z * v.z + v.w * v.w;
#pragma unroll
    for (int o = 16; o; o >>= 1) {
        s += __shfl_xor_sync(0xffffffffu, s, o);
        q += __shfl_xor_sync(0xffffffffu, q, o);
    }
    __shared__ float ss[8], sq[8];
    int warp = t >> 5, lane = t & 31;
    if (lane == 0) { ss[warp] = s; sq[warp] = q; }
    __syncthreads();
    float ts = 0.f, tq = 0.f;
#pragma unroll
    for (int ww = 0; ww < 8; ww++) { ts += ss[ww]; tq += sq[ww]; }
    float mu = ts * (1.0f / D_SZ);
    float var = tq * (1.0f / D_SZ) - mu * mu;
    float rstd = rsqrtf(var + 1e-3f);
    float4 g  = reinterpret_cast<const float4*>(gamma)[t];
    float4 be = reinterpret_cast<const float4*>(beta)[t];
    float4 o;
    o.x = (v.x - mu) * rstd * g.x + be.x;
    o.y = (v.y - mu) * rstd * g.y + be.y;
    o.z = (v.z - mu) * rstd * g.z + be.z;
    o.w = (v.w - mu) * rstd * g.w + be.w;
    reinterpret_cast<float4*>(y + (size_t)row * D_SZ)[t] = o;
}

// ---- host launcher ----------------------------------------------------------
extern "C" void kernel_launch(void* const* d_in, const int* in_sizes, int n_in,
                              void* d_out, int out_size) {
    const float* x     = (const float*)d_in[0];
    const float* Wq    = (const float*)d_in[1];
    const float* bq    = (const float*)d_in[2];
    const float* Wk    = (const float*)d_in[3];
    const float* bk    = (const float*)d_in[4];
    const float* Wv    = (const float*)d_in[5];
    const float* bv    = (const float*)d_in[6];
    const float* Wo    = (const float*)d_in[7];
    const float* bo    = (const float*)d_in[8];
    const float* gamma = (const float*)d_in[9];
    const float* beta  = (const float*)d_in[10];
    float* out = (float*)d_out;

    void *xb, *wq, *wk, *wv, *wo, *qb, *kb, *vb, *ctxb;
    cudaGetSymbolAddress(&xb, g_xb);
    cudaGetSymbolAddress(&wq, g_wq);
    cudaGetSymbolAddress(&wk, g_wk);
    cudaGetSymbolAddress(&wv, g_wv);
    cudaGetSymbolAddress(&wo, g_wo);
    cudaGetSymbolAddress(&qb, g_q);
    cudaGetSymbolAddress(&kb, g_k);
    cudaGetSymbolAddress(&vb, g_v);
    cudaGetSymbolAddress(&ctxb, g_ctx);

    cvt4_kernel<<<(M_ROWS * D_SZ / 4) / 256, 256>>>(x, (__nv_bfloat16*)xb, M_ROWS * D_SZ / 4);
    cvt4_kernel<<<(D_SZ * D_SZ / 4) / 256, 256>>>(Wq, (__nv_bfloat16*)wq, D_SZ * D_SZ / 4);
    cvt4_kernel<<<(D_SZ * D_SZ / 4) / 256, 256>>>(Wk, (__nv_bfloat16*)wk, D_SZ * D_SZ / 4);
    cvt4_kernel<<<(D_SZ * D_SZ / 4) / 256, 256>>>(Wv, (__nv_bfloat16*)wv, D_SZ * D_SZ / 4);
    cvt4_kernel<<<(D_SZ * D_SZ / 4) / 256, 256>>>(Wo, (__nv_bfloat16*)wo, D_SZ * D_SZ / 4);

    cudaFuncSetAttribute(gemm_nn_kernel<0>, cudaFuncAttributeMaxDynamicSharedMemorySize, SMEM_GEMM);
    cudaFuncSetAttribute(gemm_nn_kernel<1>, cudaFuncAttributeMaxDynamicSharedMemorySize, SMEM_GEMM);
    dim3 gg(D_SZ / BN, M_ROWS / BM);
    gemm_nn_kernel<0><<<gg, 256, SMEM_GEMM>>>((const __nv_bfloat16*)xb, (const __nv_bfloat16*)wq, bq, nullptr, qb);
    gemm_nn_kernel<0><<<gg, 256, SMEM_GEMM>>>((const __nv_bfloat16*)xb, (const __nv_bfloat16*)wk, bk, nullptr, kb);
    gemm_nn_kernel<0><<<gg, 256, SMEM_GEMM>>>((const __nv_bfloat16*)xb, (const __nv_bfloat16*)wv, bv, nullptr, vb);

    cudaFuncSetAttribute(attn_kernel, cudaFuncAttributeMaxDynamicSharedMemorySize, SMEM_ATTN);
    attn_kernel<<<dim3(SW_SZ / 64, H_SZ, B_SZ * W_SZ), 256, SMEM_ATTN>>>(
        (const __nv_bfloat16*)qb, (const __nv_bfloat16*)kb, (const __nv_bfloat16*)vb,
        (__nv_bfloat16*)ctxb);

    gemm_nn_kernel<1><<<gg, 256, SMEM_GEMM>>>((const __nv_bfloat16*)ctxb, (const __nv_bfloat16*)wo, bo, x, out);

    ln_kernel<<<M_ROWS, 256>>>(out, gamma, beta);
}